// round 12
// baseline (speedup 1.0000x reference)
#include <cuda_runtime.h>
#include <cuda_bf16.h>
#include <math.h>
#include <stdint.h>

// Problem constants
#define NB 4
#define NS 2048
#define ND 512
#define NH 8
#define HDIM 64
#define RLD 64
#define SLOPE 0.01f
#define LN_EPS 1e-5f
#define MR (NB * NS)   // 8192 rows
#define LOG2E 1.4426950408889634f

// ---------------------------------------------------------------------------
// Scratch (device globals -- no allocation allowed in kernel_launch)
// ---------------------------------------------------------------------------
__device__ __nv_bfloat16 g_h_bf [MR * ND];    // h   -> bf16
__device__ __nv_bfloat16 g_rh_bf[MR * RLD];   // rh  -> bf16
__device__ __nv_bfloat16 g_wr  [ND * ND];     // Wr  -> bf16
__device__ __nv_bfloat16 g_wrs [RLD * ND];    // Wrs*log2e -> bf16
__device__ __nv_bfloat16 g_wrt [RLD * ND];    // Wrt -> bf16
__device__ __nv_bfloat16 g_wf  [ND * ND];     // Wf  -> bf16
__device__ __nv_bfloat16 g_fr_bf [MR * ND];   // h @ Wr   [b,s,h,d]
__device__ __nv_bfloat16 g_rk_bf [MR * ND];   // rh @ (Wrs*log2e)
__device__ __nv_bfloat16 g_rq_bf [MR * ND];   // rh @ Wrt
__device__ __nv_bfloat16 g_hsa_bf[MR * ND];   // attention context
__device__ float g_sr [NB * NH * NS];         // per-key bias * log2e
__device__ float g_fh [MR * ND];              // h_sa @ Wf (fp32 for LN)

// ---------------------------------------------------------------------------
// helpers
// ---------------------------------------------------------------------------
__device__ __forceinline__ unsigned pk(float x, float y) {
    __nv_bfloat162 t = __float22bfloat162_rn(make_float2(x, y));
    return *(unsigned*)&t;
}

__device__ __forceinline__ float ex2(float x) {
    float y;
    asm("ex2.approx.f32 %0, %1;" : "=f"(y) : "f"(x));
    return y;
}

__device__ __forceinline__ void mma16(float* c, const unsigned* a,
                                      unsigned b0, unsigned b1) {
    asm volatile(
        "mma.sync.aligned.m16n8k16.row.col.f32.bf16.bf16.f32 "
        "{%0,%1,%2,%3}, {%4,%5,%6,%7}, {%8,%9}, {%0,%1,%2,%3};"
        : "+f"(c[0]), "+f"(c[1]), "+f"(c[2]), "+f"(c[3])
        : "r"(a[0]), "r"(a[1]), "r"(a[2]), "r"(a[3]), "r"(b0), "r"(b1));
}

__device__ __forceinline__ void ldm4(unsigned* r, uint32_t addr) {
    asm volatile(
        "ldmatrix.sync.aligned.m8n8.x4.shared.b16 {%0,%1,%2,%3}, [%4];"
        : "=r"(r[0]), "=r"(r[1]), "=r"(r[2]), "=r"(r[3]) : "r"(addr));
}

__device__ __forceinline__ void ldm4t(unsigned* r, uint32_t addr) {
    asm volatile(
        "ldmatrix.sync.aligned.m8n8.x4.trans.shared.b16 {%0,%1,%2,%3}, [%4];"
        : "=r"(r[0]), "=r"(r[1]), "=r"(r[2]), "=r"(r[3]) : "r"(addr));
}

__device__ __forceinline__ uint32_t s2u(const void* p) {
    return (uint32_t)__cvta_generic_to_shared(p);
}

__device__ __forceinline__ void cpa16(uint32_t smem, const void* g) {
    asm volatile("cp.async.cg.shared.global [%0], [%1], 16;" :: "r"(smem), "l"(g));
}
__device__ __forceinline__ void cpacommit() {
    asm volatile("cp.async.commit_group;");
}
__device__ __forceinline__ void cpawait() {
    asm volatile("cp.async.wait_group 0;" ::: "memory");
}

__device__ __forceinline__ float leaky(float x) {
    return x >= 0.f ? x : SLOPE * x;
}

// ---------------------------------------------------------------------------
// Fused fp32 -> bf16 conversion for all six operands (one launch).
// Segment sizes in float4 units; Wrs is pre-scaled by log2(e).
// ---------------------------------------------------------------------------
#define N_H4   1048576   // MR*ND/4
#define N_RH4  131072    // MR*RLD/4
#define N_WR4  65536     // ND*ND/4
#define N_WS4  8192      // RLD*ND/4
#define N_WT4  8192
#define N_WF4  65536
#define N_CVT_TOTAL (N_H4 + N_RH4 + N_WR4 + N_WS4 + N_WT4 + N_WF4)  // 1327104

__global__ void cvt_all(const float* __restrict__ h, const float* __restrict__ rh,
                        const float* __restrict__ Wr, const float* __restrict__ Wrs,
                        const float* __restrict__ Wrt, const float* __restrict__ Wf)
{
    int j = blockIdx.x * 256 + threadIdx.x;
    const float* src;
    __nv_bfloat16* dst;
    float scale = 1.f;
    if (j < N_H4)                 { src = h;   dst = g_h_bf; }
    else if ((j -= N_H4) < N_RH4) { src = rh;  dst = g_rh_bf; }
    else if ((j -= N_RH4) < N_WR4){ src = Wr;  dst = g_wr; }
    else if ((j -= N_WR4) < N_WS4){ src = Wrs; dst = g_wrs; scale = LOG2E; }
    else if ((j -= N_WS4) < N_WT4){ src = Wrt; dst = g_wrt; }
    else                          { j -= N_WT4; src = Wf; dst = g_wf; }
    float4 v = *(const float4*)(src + (size_t)j * 4);
    uint2 u; u.x = pk(v.x * scale, v.y * scale); u.y = pk(v.z * scale, v.w * scale);
    *(uint2*)(dst + (size_t)j * 4) = u;
}

// ---------------------------------------------------------------------------
// bf16 tensor-core GEMM: C[M,N] = A[M,K] @ W[K,N], all-bf16 operands.
// Block 128x64, BK=64, 256 threads = 8 warps (warp = m16 x n64).
// cp.async double-buffered; W natural [k][n] via ldmatrix.x4.trans.
// ---------------------------------------------------------------------------
template<bool OUT_BF, bool DO_SR>
__global__ __launch_bounds__(256) void gemm_bf(
    const __nv_bfloat16* __restrict__ A, const __nv_bfloat16* __restrict__ Wb,
    void* __restrict__ Cp, const float* __restrict__ ar,
    float* __restrict__ srb, int M, int N, int K)
{
    extern __shared__ unsigned smu[];
    unsigned* a2 = smu;              // 2 x 4608
    unsigned* w2 = smu + 2 * 4608;   // 2 x 2304
    const int tid = threadIdx.x;
    const int lane = tid & 31, w = tid >> 5;
    const int g = lane >> 2, t4 = lane & 3;
    const int row0 = blockIdx.y * 128, col0 = blockIdx.x * 64;
    const int m0 = w * 16;

    const int rowA = (lane & 7) + ((lane >> 3) & 1) * 8;
    const int prA  = (lane >> 4) * 4;
    const uint32_t aS = s2u(a2), wS = s2u(w2);
    const uint32_t aAddr = aS + (((m0 + rowA) * 36 + prA) << 2);
    const uint32_t wAddr = wS + ((rowA * 36 + prA) << 2);   // trans pattern

    auto prefetch = [&](int k0, int buf) {
#pragma unroll
        for (int p = 0; p < 4; p++) {
            int idx = tid + p * 256;
            int r = idx >> 3, c = idx & 7;
            cpa16(aS + buf * 18432 + ((r * 36 + c * 4) << 2),
                  A + (size_t)(row0 + r) * K + k0 + c * 8);
        }
#pragma unroll
        for (int p = 0; p < 2; p++) {
            int idx = tid + p * 256;
            int r = idx >> 3, c = idx & 7;
            cpa16(wS + buf * 9216 + ((r * 36 + c * 4) << 2),
                  Wb + (size_t)(k0 + r) * N + col0 + c * 8);
        }
    };

    float acc[8][4];
#pragma unroll
    for (int nt = 0; nt < 8; nt++)
#pragma unroll
        for (int j = 0; j < 4; j++) acc[nt][j] = 0.f;

    prefetch(0, 0); cpacommit();
    int pb = 0;
    const int KT = K >> 6;
    for (int kt = 0; kt < KT; kt++) {
        cpawait(); __syncthreads();
        if (kt + 1 < KT) { prefetch((kt + 1) * 64, pb ^ 1); cpacommit(); }
#pragma unroll
        for (int ks = 0; ks < 4; ks++) {
            unsigned Aq[4];
            ldm4(Aq, aAddr + pb * 18432 + ks * 32);
#pragma unroll
            for (int ntp = 0; ntp < 4; ntp++) {
                unsigned Bw[4];
                ldm4t(Bw, wAddr + pb * 9216 + ks * 2304 + ntp * 32);
                mma16(acc[2 * ntp],     Aq, Bw[0], Bw[1]);
                mma16(acc[2 * ntp + 1], Aq, Bw[2], Bw[3]);
            }
        }
        pb ^= 1;
    }

    if (OUT_BF) {
        unsigned* Cb = (unsigned*)Cp;
#pragma unroll
        for (int nt = 0; nt < 8; nt++) {
            int r = row0 + m0 + g;
            int c = col0 + nt * 8 + 2 * t4;
            Cb[((size_t)r * N + c) >> 1] = pk(acc[nt][0], acc[nt][1]);
            Cb[((size_t)(r + 8) * N + c) >> 1] = pk(acc[nt][2], acc[nt][3]);
        }
    } else {
        float* Cf = (float*)Cp;
#pragma unroll
        for (int nt = 0; nt < 8; nt++) {
            int r = row0 + m0 + g;
            int c = col0 + nt * 8 + 2 * t4;
            float2 lo; lo.x = acc[nt][0]; lo.y = acc[nt][1];
            float2 hi; hi.x = acc[nt][2]; hi.y = acc[nt][3];
            *(float2*)(Cf + (size_t)r * N + c) = lo;
            *(float2*)(Cf + (size_t)(r + 8) * N + c) = hi;
        }
    }

    if (DO_SR) {
        // col block == one head: h = blockIdx.x; emit sr * log2e
        float sm2[2] = {0.f, 0.f};
#pragma unroll
        for (int nt = 0; nt < 8; nt++) {
            float2 av = *(const float2*)&ar[nt * 8 + 2 * t4];
            sm2[0] += leaky(acc[nt][0]) * av.x + leaky(acc[nt][1]) * av.y;
            sm2[1] += leaky(acc[nt][2]) * av.x + leaky(acc[nt][3]) * av.y;
        }
#pragma unroll
        for (int i = 0; i < 2; i++) {
            sm2[i] += __shfl_xor_sync(0xffffffffu, sm2[i], 1);
            sm2[i] += __shfl_xor_sync(0xffffffffu, sm2[i], 2);
        }
        if (t4 == 0) {
            int hh = blockIdx.x;
#pragma unroll
            for (int i = 0; i < 2; i++) {
                int r = row0 + m0 + i * 8 + g;
                int bb = r >> 11, t = r & (NS - 1);
                srb[((size_t)bb * NH + hh) * NS + t] = sm2[i] * LOG2E;
            }
        }
    }
}

// ---------------------------------------------------------------------------
// Dual-output K=64 GEMM: rk = rh @ Wrs', rq = rh @ Wrt  (shared A tile).
// ---------------------------------------------------------------------------
__global__ __launch_bounds__(256) void gemm_rkq(
    const __nv_bfloat16* __restrict__ A,
    const __nv_bfloat16* __restrict__ W1, const __nv_bfloat16* __restrict__ W2,
    __nv_bfloat16* __restrict__ C1, __nv_bfloat16* __restrict__ C2)
{
    __shared__ unsigned a2[4608];
    __shared__ unsigned w1[2304];
    __shared__ unsigned w2[2304];
    const int tid = threadIdx.x;
    const int lane = tid & 31, w = tid >> 5;
    const int g = lane >> 2, t4 = lane & 3;
    const int row0 = blockIdx.y * 128, col0 = blockIdx.x * 64;
    const int m0 = w * 16;

    const int rowA = (lane & 7) + ((lane >> 3) & 1) * 8;
    const int prA  = (lane >> 4) * 4;
    const uint32_t aS = s2u(a2), w1S = s2u(w1), w2S = s2u(w2);
    const uint32_t aAddr  = aS  + (((m0 + rowA) * 36 + prA) << 2);
    const uint32_t w1Addr = w1S + ((rowA * 36 + prA) << 2);
    const uint32_t w2Addr = w2S + ((rowA * 36 + prA) << 2);

#pragma unroll
    for (int p = 0; p < 4; p++) {
        int idx = tid + p * 256;
        int r = idx >> 3, c = idx & 7;
        cpa16(aS + ((r * 36 + c * 4) << 2), A + (size_t)(row0 + r) * RLD + c * 8);
    }
#pragma unroll
    for (int p = 0; p < 2; p++) {
        int idx = tid + p * 256;
        int r = idx >> 3, c = idx & 7;
        uint32_t off = (uint32_t)((r * 36 + c * 4) << 2);
        size_t goff = (size_t)r * ND + col0 + c * 8;
        cpa16(w1S + off, W1 + goff);
        cpa16(w2S + off, W2 + goff);
    }
    cpacommit(); cpawait(); __syncthreads();

    float acc1[8][4], acc2[8][4];
#pragma unroll
    for (int nt = 0; nt < 8; nt++)
#pragma unroll
        for (int j = 0; j < 4; j++) { acc1[nt][j] = 0.f; acc2[nt][j] = 0.f; }

#pragma unroll
    for (int ks = 0; ks < 4; ks++) {
        unsigned Aq[4];
        ldm4(Aq, aAddr + ks * 32);
#pragma unroll
        for (int ntp = 0; ntp < 4; ntp++) {
            unsigned B1[4], B2[4];
            ldm4t(B1, w1Addr + ks * 2304 + ntp * 32);
            ldm4t(B2, w2Addr + ks * 2304 + ntp * 32);
            mma16(acc1[2 * ntp],     Aq, B1[0], B1[1]);
            mma16(acc1[2 * ntp + 1], Aq, B1[2], B1[3]);
            mma16(acc2[2 * ntp],     Aq, B2[0], B2[1]);
            mma16(acc2[2 * ntp + 1], Aq, B2[2], B2[3]);
        }
    }

    unsigned* C1b = (unsigned*)C1;
    unsigned* C2b = (unsigned*)C2;
#pragma unroll
    for (int nt = 0; nt < 8; nt++) {
        int r = row0 + m0 + g;
        int c = col0 + nt * 8 + 2 * t4;
        size_t i0 = ((size_t)r * ND + c) >> 1;
        size_t i1 = ((size_t)(r + 8) * ND + c) >> 1;
        C1b[i0] = pk(acc1[nt][0], acc1[nt][1]);
        C1b[i1] = pk(acc1[nt][2], acc1[nt][3]);
        C2b[i0] = pk(acc2[nt][0], acc2[nt][1]);
        C2b[i1] = pk(acc2[nt][2], acc2[nt][3]);
    }
}

// ---------------------------------------------------------------------------
// bf16 flash attention (no-max streaming softmax; log2e pre-folded):
//   hsa = softmax_t(rk.rq^T + sr[t]) @ fr       (softmax via bare ex2)
// Block: 128 Q rows, 4 warps x m32 (two m16 halves mt=0,1), 128 threads,
// 4 CTAs/SM. 64-key double-buffered tiles processed in two 32-key passes;
// within a pass K/V fragments are reused across both m16 halves, amortizing
// smem crossbar traffic over 32 rows (0.75 KB/row/64keys vs 1.125 before).
// smem u32: q2[128][36] | k2 2x[64][36] | v2 2x[64][36] | sr 2x[64]
// ---------------------------------------------------------------------------
__global__ __launch_bounds__(128, 4) void attn_bf16(
    const __nv_bfloat16* __restrict__ rk, const __nv_bfloat16* __restrict__ rq,
    const __nv_bfloat16* __restrict__ fr, const float* __restrict__ srb,
    __nv_bfloat16* __restrict__ hsa)
{
    extern __shared__ unsigned smu[];
    unsigned* q2 = smu;                    // [128][36]
    unsigned* k2 = q2 + 4608;              // 2 x [64][36]
    unsigned* v2 = k2 + 2 * 2304;          // 2 x [64][36] natural [t][d]
    float*  sr_s = (float*)(v2 + 2 * 2304);// 2 x [64]

    const int tid = threadIdx.x;
    const int lane = tid & 31, w = tid >> 5;
    const int g = lane >> 2, t4 = lane & 3;
    const int s0 = blockIdx.x * 128;
    const int h = blockIdx.y, b = blockIdx.z;
    const int m0 = w * 32;                 // warp covers rows m0..m0+31

    const int rowA = (lane & 7) + ((lane >> 3) & 1) * 8;
    const int prA  = (lane >> 4) * 4;
    const int rowB = (lane & 7) + (lane >> 4) * 8;
    const int prB  = ((lane >> 3) & 1) * 4;
    const uint32_t qS = s2u(q2), kS = s2u(k2), vS = s2u(v2);
    const uint32_t srS = s2u(sr_s);
    const uint32_t qAddr0 = qS + (((m0 + rowA) * 36 + prA) << 2);        // mt=0
    const uint32_t qAddr1 = qS + (((m0 + 16 + rowA) * 36 + prA) << 2);   // mt=1
    const uint32_t kAddr = kS + ((rowB * 36 + prB) << 2);
    const uint32_t vAddr = vS + ((rowA * 36 + prA) << 2);   // trans pattern

    const __nv_bfloat16* qg = rk + (size_t)(b * NS + s0) * ND + h * HDIM;
    const __nv_bfloat16* kg = rq + (size_t)b * NS * ND + h * HDIM;
    const __nv_bfloat16* vg = fr + (size_t)b * NS * ND + h * HDIM;
    const float* srr = srb + ((size_t)b * NH + h) * NS;

    auto prefetch = [&](int t0p, int buf) {
#pragma unroll
        for (int p = 0; p < 4; p++) {
            int idx = tid + p * 128;          // 0..511
            int key = idx >> 3, c = idx & 7;  // key 0..63
            uint32_t off = (uint32_t)((key * 36 + c * 4) << 2);
            size_t goff = (size_t)(t0p + key) * ND + c * 8;
            cpa16(kS + buf * 9216 + off, kg + goff);
            cpa16(vS + buf * 9216 + off, vg + goff);
        }
        if (tid < 16) cpa16(srS + buf * 256 + tid * 16, srr + t0p + tid * 4);
    };

    // Stage Q via cp.async (128 rows x 8 uint4)
#pragma unroll
    for (int p = 0; p < 8; p++) {
        int idx = tid + p * 128;
        int r = idx >> 3, c = idx & 7;
        cpa16(qS + ((r * 36 + c * 4) << 2), qg + (size_t)r * ND + c * 8);
    }
    prefetch(0, 0); cpacommit();

    float o[2][8][4];
    float lsum[4] = {0.f, 0.f, 0.f, 0.f};
#pragma unroll
    for (int mt = 0; mt < 2; mt++)
#pragma unroll
        for (int nt = 0; nt < 8; nt++)
#pragma unroll
            for (int j = 0; j < 4; j++) o[mt][nt][j] = 0.f;

    int pb = 0;
    for (int t0 = 0; t0 < NS; t0 += 64) {
        cpawait(); __syncthreads();
        if (t0 + 64 < NS) { prefetch(t0 + 64, pb ^ 1); cpacommit(); }

#pragma unroll
        for (int pass = 0; pass < 2; pass++) {   // 32 keys per pass
            // ---- S = Q @ K^T for both m16 halves (K frags reused) ----
            float s[2][4][4];
#pragma unroll
            for (int mt = 0; mt < 2; mt++)
#pragma unroll
                for (int nt = 0; nt < 4; nt++)
#pragma unroll
                    for (int j = 0; j < 4; j++) s[mt][nt][j] = 0.f;
#pragma unroll
            for (int ks = 0; ks < 4; ks++) {
                unsigned Aq0[4], Aq1[4];
                ldm4(Aq0, qAddr0 + ks * 32);
                ldm4(Aq1, qAddr1 + ks * 32);
#pragma unroll
                for (int ntp = 0; ntp < 2; ntp++) {
                    unsigned Bk[4];
                    ldm4(Bk, kAddr + pb * 9216 + (pass * 2 + ntp) * 2304 + ks * 32);
                    mma16(s[0][2 * ntp],     Aq0, Bk[0], Bk[1]);
                    mma16(s[0][2 * ntp + 1], Aq0, Bk[2], Bk[3]);
                    mma16(s[1][2 * ntp],     Aq1, Bk[0], Bk[1]);
                    mma16(s[1][2 * ntp + 1], Aq1, Bk[2], Bk[3]);
                }
            }

            // ---- bias + ex2 (no-max softmax; log2e pre-folded) ----
            const float* srt = sr_s + pb * 64 + pass * 32;
            unsigned plo[2][4], phi[2][4];
#pragma unroll
            for (int mt = 0; mt < 2; mt++)
#pragma unroll
                for (int nt = 0; nt < 4; nt++) {
                    float2 bi = *(const float2*)&srt[nt * 8 + 2 * t4];
                    float p0 = ex2(s[mt][nt][0] + bi.x);
                    float p1 = ex2(s[mt][nt][1] + bi.y);
                    float q0 = ex2(s[mt][nt][2] + bi.x);
                    float q1 = ex2(s[mt][nt][3] + bi.y);
                    lsum[mt * 2 + 0] += p0 + p1;
                    lsum[mt * 2 + 1] += q0 + q1;
                    plo[mt][nt] = pk(p0, p1);
                    phi[mt][nt] = pk(q0, q1);
                }

            // ---- O += P @ V for both halves (V frags reused) ----
#pragma unroll
            for (int ks = 0; ks < 2; ks++) {     // 2 chunks of 16 keys
                unsigned Ap0[4] = {plo[0][2 * ks], phi[0][2 * ks],
                                   plo[0][2 * ks + 1], phi[0][2 * ks + 1]};
                unsigned Ap1[4] = {plo[1][2 * ks], phi[1][2 * ks],
                                   plo[1][2 * ks + 1], phi[1][2 * ks + 1]};
#pragma unroll
                for (int ntp = 0; ntp < 4; ntp++) {
                    unsigned Bv[4];
                    ldm4t(Bv, vAddr + pb * 9216 + (pass * 2 + ks) * 2304 + ntp * 32);
                    mma16(o[0][2 * ntp],     Ap0, Bv[0], Bv[1]);
                    mma16(o[0][2 * ntp + 1], Ap0, Bv[2], Bv[3]);
                    mma16(o[1][2 * ntp],     Ap1, Bv[0], Bv[1]);
                    mma16(o[1][2 * ntp + 1], Ap1, Bv[2], Bv[3]);
                }
            }
        }
        pb ^= 1;
    }

    // Epilogue: deferred row-sum reduce, normalize, store bf16 hsa
#pragma unroll
    for (int i = 0; i < 4; i++) {
        lsum[i] += __shfl_xor_sync(0xffffffffu, lsum[i], 1);
        lsum[i] += __shfl_xor_sync(0xffffffffu, lsum[i], 2);
        lsum[i] = 1.0f / lsum[i];
    }
    unsigned* Hb = (unsigned*)hsa;
#pragma unroll
    for (int mt = 0; mt < 2; mt++)
#pragma unroll
        for (int nt = 0; nt < 8; nt++) {
            int r = s0 + m0 + mt * 16 + g;
            int col = h * HDIM + nt * 8 + 2 * t4;
            Hb[((size_t)(b * NS + r) * ND + col) >> 1] =
                pk(o[mt][nt][0] * lsum[mt * 2], o[mt][nt][1] * lsum[mt * 2]);
            Hb[((size_t)(b * NS + r + 8) * ND + col) >> 1] =
                pk(o[mt][nt][2] * lsum[mt * 2 + 1], o[mt][nt][3] * lsum[mt * 2 + 1]);
        }
}

// ---------------------------------------------------------------------------
// out = LayerNorm(h + fh) * g + b     (one warp per row of 512)
// ---------------------------------------------------------------------------
__global__ void ln_kernel(const float* __restrict__ hin,
                          const float* __restrict__ fh,
                          const float* __restrict__ g,
                          const float* __restrict__ be,
                          float* __restrict__ out)
{
    int warp = threadIdx.x >> 5, lane = threadIdx.x & 31;
    int row = blockIdx.x * 8 + warp;
    const float* hr = hin + (size_t)row * ND;
    const float* fr = fh  + (size_t)row * ND;

    float x[16];
    float sum = 0.f;
#pragma unroll
    for (int i = 0; i < 16; i++) {
        int d = lane + i * 32;
        x[i] = hr[d] + fr[d];
        sum += x[i];
    }
#pragma unroll
    for (int m = 16; m > 0; m >>= 1) sum += __shfl_xor_sync(0xffffffffu, sum, m);
    float mu = sum * (1.0f / ND);
    float vs = 0.f;
#pragma unroll
    for (int i = 0; i < 16; i++) { float d = x[i] - mu; vs += d * d; }
#pragma unroll
    for (int m = 16; m > 0; m >>= 1) vs += __shfl_xor_sync(0xffffffffu, vs, m);
    float rstd = rsqrtf(vs * (1.0f / ND) + LN_EPS);
#pragma unroll
    for (int i = 0; i < 16; i++) {
        int d = lane + i * 32;
        out[(size_t)row * ND + d] = (x[i] - mu) * rstd * g[d] + be[d];
    }
}

// ---------------------------------------------------------------------------
// kernel_launch
// Inputs: 0:h 1:rh 2:Wl(unused) 3:Wr 4:al(unused) 5:ar 6:Wrs 7:Wrt 8:Wf 9:ln_g 10:ln_b
// ---------------------------------------------------------------------------
extern "C" void kernel_launch(void* const* d_in, const int* in_sizes, int n_in,
                              void* d_out, int out_size)
{
    const float* h    = (const float*)d_in[0];
    const float* rh   = (const float*)d_in[1];
    const float* Wr   = (const float*)d_in[3];
    const float* ar   = (const float*)d_in[5];
    const float* Wrs  = (const float*)d_in[6];
    const float* Wrt  = (const float*)d_in[7];
    const float* Wf   = (const float*)d_in[8];
    const float* ln_g = (const float*)d_in[9];
    const float* ln_b = (const float*)d_in[10];
    float* out = (float*)d_out;

    __nv_bfloat16 *hb, *rhb, *wrb, *wrsb, *wrtb, *wfb;
    __nv_bfloat16 *frb, *rkb, *rqb, *hsab;
    float *srb, *fh;
    cudaGetSymbolAddress((void**)&hb,   g_h_bf);
    cudaGetSymbolAddress((void**)&rhb,  g_rh_bf);
    cudaGetSymbolAddress((void**)&wrb,  g_wr);
    cudaGetSymbolAddress((void**)&wrsb, g_wrs);
    cudaGetSymbolAddress((void**)&wrtb, g_wrt);
    cudaGetSymbolAddress((void**)&wfb,  g_wf);
    cudaGetSymbolAddress((void**)&frb,  g_fr_bf);
    cudaGetSymbolAddress((void**)&rkb,  g_rk_bf);
    cudaGetSymbolAddress((void**)&rqb,  g_rq_bf);
    cudaGetSymbolAddress((void**)&hsab, g_hsa_bf);
    cudaGetSymbolAddress((void**)&srb,  g_sr);
    cudaGetSymbolAddress((void**)&fh,   g_fh);

    const int smem_gemm = (2 * 4608 + 2 * 2304) * (int)sizeof(unsigned);     // 55296
    const int smem_attn = (4608 + 2 * 2304 + 2 * 2304 + 128) * 4;            // 55808
    cudaFuncSetAttribute(gemm_bf<true,  true >, cudaFuncAttributeMaxDynamicSharedMemorySize, smem_gemm);
    cudaFuncSetAttribute(gemm_bf<false, false>, cudaFuncAttributeMaxDynamicSharedMemorySize, smem_gemm);
    cudaFuncSetAttribute(attn_bf16, cudaFuncAttributeMaxDynamicSharedMemorySize, smem_attn);

    // Single fused fp32 -> bf16 conversion pass (Wrs pre-scaled by log2e)
    cvt_all<<<N_CVT_TOTAL / 256, 256>>>(h, rh, Wr, Wrs, Wrt, Wf);

    dim3 blk(256);
    dim3 gproj(ND / 64, MR / 128);
    // fr projection + fused sr epilogue (fl/sl dropped: softmax shift-invariance)
    gemm_bf<true,  true ><<<gproj, blk, smem_gemm>>>(hb,  wrb,  frb, ar, srb, MR, ND, ND);
    // rk/rq dual-output projection (shared rh tile)
    gemm_rkq<<<gproj, blk>>>(rhb, wrsb, wrtb, rkb, rqb);
    // bf16 flash attention: 4 warps x m32, 4 CTAs/SM, one wave
    attn_bf16<<<dim3(NS / 128, NH, NB), 128, smem_attn>>>(rkb, rqb, frb, srb, hsab);
    // Output projection + residual LayerNorm
    gemm_bf<false, false><<<gproj, blk, smem_gemm>>>(hsab, wfb, fh, nullptr, nullptr, MR, ND, ND);
    ln_kernel<<<MR / 8, 256>>>(h, fh, ln_g, ln_b, out);
}

// round 13
// speedup vs baseline: 1.1184x; 1.1184x over previous
#include <cuda_runtime.h>
#include <cuda_bf16.h>
#include <math.h>
#include <stdint.h>

// Problem constants
#define NB 4
#define NS 2048
#define ND 512
#define NH 8
#define HDIM 64
#define RLD 64
#define SLOPE 0.01f
#define LN_EPS 1e-5f
#define MR (NB * NS)   // 8192 rows
#define LOG2E 1.4426950408889634f

// ---------------------------------------------------------------------------
// Scratch (device globals -- no allocation allowed in kernel_launch)
// ---------------------------------------------------------------------------
__device__ __nv_bfloat16 g_h_bf [MR * ND];    // h   -> bf16
__device__ __nv_bfloat16 g_rh_bf[MR * RLD];   // rh  -> bf16
__device__ __nv_bfloat16 g_wr  [ND * ND];     // Wr  -> bf16
__device__ __nv_bfloat16 g_wrs [RLD * ND];    // Wrs*log2e -> bf16
__device__ __nv_bfloat16 g_wrt [RLD * ND];    // Wrt -> bf16
__device__ __nv_bfloat16 g_wf  [ND * ND];     // Wf  -> bf16
__device__ __nv_bfloat16 g_fr_bf [MR * ND];   // h @ Wr   [b,s,h,d]
__device__ __nv_bfloat16 g_rk_bf [MR * ND];   // rh @ (Wrs*log2e)
__device__ __nv_bfloat16 g_rq_bf [MR * ND];   // rh @ Wrt
__device__ __nv_bfloat16 g_hsa_bf[MR * ND];   // attention context
__device__ float g_sr [NB * NH * NS];         // per-key bias * log2e
__device__ float g_fh [MR * ND];              // h_sa @ Wf (fp32 for LN)

// ---------------------------------------------------------------------------
// helpers
// ---------------------------------------------------------------------------
__device__ __forceinline__ unsigned pk(float x, float y) {
    __nv_bfloat162 t = __float22bfloat162_rn(make_float2(x, y));
    return *(unsigned*)&t;
}

__device__ __forceinline__ float ex2(float x) {
    float y;
    asm("ex2.approx.f32 %0, %1;" : "=f"(y) : "f"(x));
    return y;
}

__device__ __forceinline__ void mma16(float* c, const unsigned* a,
                                      unsigned b0, unsigned b1) {
    asm volatile(
        "mma.sync.aligned.m16n8k16.row.col.f32.bf16.bf16.f32 "
        "{%0,%1,%2,%3}, {%4,%5,%6,%7}, {%8,%9}, {%0,%1,%2,%3};"
        : "+f"(c[0]), "+f"(c[1]), "+f"(c[2]), "+f"(c[3])
        : "r"(a[0]), "r"(a[1]), "r"(a[2]), "r"(a[3]), "r"(b0), "r"(b1));
}

__device__ __forceinline__ void ldm4(unsigned* r, uint32_t addr) {
    asm volatile(
        "ldmatrix.sync.aligned.m8n8.x4.shared.b16 {%0,%1,%2,%3}, [%4];"
        : "=r"(r[0]), "=r"(r[1]), "=r"(r[2]), "=r"(r[3]) : "r"(addr));
}

__device__ __forceinline__ void ldm4t(unsigned* r, uint32_t addr) {
    asm volatile(
        "ldmatrix.sync.aligned.m8n8.x4.trans.shared.b16 {%0,%1,%2,%3}, [%4];"
        : "=r"(r[0]), "=r"(r[1]), "=r"(r[2]), "=r"(r[3]) : "r"(addr));
}

__device__ __forceinline__ uint32_t s2u(const void* p) {
    return (uint32_t)__cvta_generic_to_shared(p);
}

__device__ __forceinline__ void cpa16(uint32_t smem, const void* g) {
    asm volatile("cp.async.cg.shared.global [%0], [%1], 16;" :: "r"(smem), "l"(g));
}
__device__ __forceinline__ void cpacommit() {
    asm volatile("cp.async.commit_group;");
}
__device__ __forceinline__ void cpawait() {
    asm volatile("cp.async.wait_group 0;" ::: "memory");
}

__device__ __forceinline__ float leaky(float x) {
    return x >= 0.f ? x : SLOPE * x;
}

// ---------------------------------------------------------------------------
// Fused fp32 -> bf16 conversion for all six operands (one launch).
// Segment sizes in float4 units; Wrs is pre-scaled by log2(e).
// ---------------------------------------------------------------------------
#define N_H4   1048576   // MR*ND/4
#define N_RH4  131072    // MR*RLD/4
#define N_WR4  65536     // ND*ND/4
#define N_WS4  8192      // RLD*ND/4
#define N_WT4  8192
#define N_WF4  65536
#define N_CVT_TOTAL (N_H4 + N_RH4 + N_WR4 + N_WS4 + N_WT4 + N_WF4)  // 1327104

__global__ void cvt_all(const float* __restrict__ h, const float* __restrict__ rh,
                        const float* __restrict__ Wr, const float* __restrict__ Wrs,
                        const float* __restrict__ Wrt, const float* __restrict__ Wf)
{
    int j = blockIdx.x * 256 + threadIdx.x;
    const float* src;
    __nv_bfloat16* dst;
    float scale = 1.f;
    if (j < N_H4)                 { src = h;   dst = g_h_bf; }
    else if ((j -= N_H4) < N_RH4) { src = rh;  dst = g_rh_bf; }
    else if ((j -= N_RH4) < N_WR4){ src = Wr;  dst = g_wr; }
    else if ((j -= N_WR4) < N_WS4){ src = Wrs; dst = g_wrs; scale = LOG2E; }
    else if ((j -= N_WS4) < N_WT4){ src = Wrt; dst = g_wrt; }
    else                          { j -= N_WT4; src = Wf; dst = g_wf; }
    float4 v = *(const float4*)(src + (size_t)j * 4);
    uint2 u; u.x = pk(v.x * scale, v.y * scale); u.y = pk(v.z * scale, v.w * scale);
    *(uint2*)(dst + (size_t)j * 4) = u;
}

// ---------------------------------------------------------------------------
// bf16 tensor-core GEMM: C[M,N] = A[M,K] @ W[K,N], all-bf16 operands.
// Block 128x128 (one wave for M=8192,N=512), BK=64, 256 threads = 8 warps
// (warp = m16 x n128, acc 64 regs). cp.async double-buffered.
// A [row][k-pair] pitch 36 wds; W natural [k][n] pitch 68 wds via
// ldmatrix.x4.trans (pitch = 4 mod 32 words -> conflict-free).
// DO_SR: N-tile spans TWO heads (2 x HDIM); epilogue splits at nt=8.
// ---------------------------------------------------------------------------
template<bool OUT_BF, bool DO_SR>
__global__ __launch_bounds__(256) void gemm_bf(
    const __nv_bfloat16* __restrict__ A, const __nv_bfloat16* __restrict__ Wb,
    void* __restrict__ Cp, const float* __restrict__ ar,
    float* __restrict__ srb, int M, int N, int K)
{
    extern __shared__ unsigned smu[];
    unsigned* a2 = smu;              // 2 x 4608  (buffer stride 18432 B)
    unsigned* w2 = smu + 2 * 4608;   // 2 x 4352  (buffer stride 17408 B)
    const int tid = threadIdx.x;
    const int lane = tid & 31, w = tid >> 5;
    const int g = lane >> 2, t4 = lane & 3;
    const int row0 = blockIdx.y * 128, col0 = blockIdx.x * 128;
    const int m0 = w * 16;

    const int rowA = (lane & 7) + ((lane >> 3) & 1) * 8;
    const int prA  = (lane >> 4) * 4;
    const uint32_t aS = s2u(a2), wS = s2u(w2);
    const uint32_t aAddr = aS + (((m0 + rowA) * 36 + prA) << 2);
    const uint32_t wAddr = wS + ((rowA * 68 + prA) << 2);   // trans pattern

    auto prefetch = [&](int k0, int buf) {
#pragma unroll
        for (int p = 0; p < 4; p++) {          // A: 128 rows x 64 k
            int idx = tid + p * 256;
            int r = idx >> 3, c = idx & 7;
            cpa16(aS + buf * 18432 + ((r * 36 + c * 4) << 2),
                  A + (size_t)(row0 + r) * K + k0 + c * 8);
        }
#pragma unroll
        for (int p = 0; p < 4; p++) {          // W: 64 k x 128 n
            int idx = tid + p * 256;
            int r = idx >> 4, c = idx & 15;
            cpa16(wS + buf * 17408 + ((r * 68 + c * 4) << 2),
                  Wb + (size_t)(k0 + r) * N + col0 + c * 8);
        }
    };

    float acc[16][4];
#pragma unroll
    for (int nt = 0; nt < 16; nt++)
#pragma unroll
        for (int j = 0; j < 4; j++) acc[nt][j] = 0.f;

    prefetch(0, 0); cpacommit();
    int pb = 0;
    const int KT = K >> 6;
    for (int kt = 0; kt < KT; kt++) {
        cpawait(); __syncthreads();
        if (kt + 1 < KT) { prefetch((kt + 1) * 64, pb ^ 1); cpacommit(); }
#pragma unroll
        for (int ks = 0; ks < 4; ks++) {
            unsigned Aq[4];
            ldm4(Aq, aAddr + pb * 18432 + ks * 32);
#pragma unroll
            for (int ntp = 0; ntp < 8; ntp++) {
                unsigned Bw[4];
                ldm4t(Bw, wAddr + pb * 17408 + ks * 4352 + ntp * 32);
                mma16(acc[2 * ntp],     Aq, Bw[0], Bw[1]);
                mma16(acc[2 * ntp + 1], Aq, Bw[2], Bw[3]);
            }
        }
        pb ^= 1;
    }

    if (OUT_BF) {
        unsigned* Cb = (unsigned*)Cp;
#pragma unroll
        for (int nt = 0; nt < 16; nt++) {
            int r = row0 + m0 + g;
            int c = col0 + nt * 8 + 2 * t4;
            Cb[((size_t)r * N + c) >> 1] = pk(acc[nt][0], acc[nt][1]);
            Cb[((size_t)(r + 8) * N + c) >> 1] = pk(acc[nt][2], acc[nt][3]);
        }
    } else {
        float* Cf = (float*)Cp;
#pragma unroll
        for (int nt = 0; nt < 16; nt++) {
            int r = row0 + m0 + g;
            int c = col0 + nt * 8 + 2 * t4;
            float2 lo; lo.x = acc[nt][0]; lo.y = acc[nt][1];
            float2 hi; hi.x = acc[nt][2]; hi.y = acc[nt][3];
            *(float2*)(Cf + (size_t)r * N + c) = lo;
            *(float2*)(Cf + (size_t)(r + 8) * N + c) = hi;
        }
    }

    if (DO_SR) {
        // N-tile = 2 heads: head hh = col0/64 + (nt>=8); d = (nt&7)*8 + 2*t4
        float sm[2][2] = {{0.f, 0.f}, {0.f, 0.f}};
#pragma unroll
        for (int nt = 0; nt < 16; nt++) {
            int hh = nt >> 3;
            float2 av = *(const float2*)&ar[(nt & 7) * 8 + 2 * t4];
            sm[hh][0] += leaky(acc[nt][0]) * av.x + leaky(acc[nt][1]) * av.y;
            sm[hh][1] += leaky(acc[nt][2]) * av.x + leaky(acc[nt][3]) * av.y;
        }
#pragma unroll
        for (int hh = 0; hh < 2; hh++)
#pragma unroll
            for (int i = 0; i < 2; i++) {
                sm[hh][i] += __shfl_xor_sync(0xffffffffu, sm[hh][i], 1);
                sm[hh][i] += __shfl_xor_sync(0xffffffffu, sm[hh][i], 2);
            }
        if (t4 == 0) {
            int hbase = col0 / HDIM;
#pragma unroll
            for (int hh = 0; hh < 2; hh++)
#pragma unroll
                for (int i = 0; i < 2; i++) {
                    int r = row0 + m0 + i * 8 + g;
                    int bb = r >> 11, t = r & (NS - 1);
                    srb[((size_t)bb * NH + hbase + hh) * NS + t] = sm[hh][i] * LOG2E;
                }
        }
    }
}

// ---------------------------------------------------------------------------
// Dual-output K=64 GEMM: rk = rh @ Wrs', rq = rh @ Wrt  (shared A tile).
// Block 128 rows x 64 cols, 256 threads = 8 warps (warp = m16 x n64).
// ---------------------------------------------------------------------------
__global__ __launch_bounds__(256) void gemm_rkq(
    const __nv_bfloat16* __restrict__ A,
    const __nv_bfloat16* __restrict__ W1, const __nv_bfloat16* __restrict__ W2,
    __nv_bfloat16* __restrict__ C1, __nv_bfloat16* __restrict__ C2)
{
    __shared__ unsigned a2[4608];
    __shared__ unsigned w1[2304];
    __shared__ unsigned w2[2304];
    const int tid = threadIdx.x;
    const int lane = tid & 31, w = tid >> 5;
    const int g = lane >> 2, t4 = lane & 3;
    const int row0 = blockIdx.y * 128, col0 = blockIdx.x * 64;
    const int m0 = w * 16;

    const int rowA = (lane & 7) + ((lane >> 3) & 1) * 8;
    const int prA  = (lane >> 4) * 4;
    const uint32_t aS = s2u(a2), w1S = s2u(w1), w2S = s2u(w2);
    const uint32_t aAddr  = aS  + (((m0 + rowA) * 36 + prA) << 2);
    const uint32_t w1Addr = w1S + ((rowA * 36 + prA) << 2);
    const uint32_t w2Addr = w2S + ((rowA * 36 + prA) << 2);

#pragma unroll
    for (int p = 0; p < 4; p++) {
        int idx = tid + p * 256;
        int r = idx >> 3, c = idx & 7;
        cpa16(aS + ((r * 36 + c * 4) << 2), A + (size_t)(row0 + r) * RLD + c * 8);
    }
#pragma unroll
    for (int p = 0; p < 2; p++) {
        int idx = tid + p * 256;
        int r = idx >> 3, c = idx & 7;
        uint32_t off = (uint32_t)((r * 36 + c * 4) << 2);
        size_t goff = (size_t)r * ND + col0 + c * 8;
        cpa16(w1S + off, W1 + goff);
        cpa16(w2S + off, W2 + goff);
    }
    cpacommit(); cpawait(); __syncthreads();

    float acc1[8][4], acc2[8][4];
#pragma unroll
    for (int nt = 0; nt < 8; nt++)
#pragma unroll
        for (int j = 0; j < 4; j++) { acc1[nt][j] = 0.f; acc2[nt][j] = 0.f; }

#pragma unroll
    for (int ks = 0; ks < 4; ks++) {
        unsigned Aq[4];
        ldm4(Aq, aAddr + ks * 32);
#pragma unroll
        for (int ntp = 0; ntp < 4; ntp++) {
            unsigned B1[4], B2[4];
            ldm4t(B1, w1Addr + ks * 2304 + ntp * 32);
            ldm4t(B2, w2Addr + ks * 2304 + ntp * 32);
            mma16(acc1[2 * ntp],     Aq, B1[0], B1[1]);
            mma16(acc1[2 * ntp + 1], Aq, B1[2], B1[3]);
            mma16(acc2[2 * ntp],     Aq, B2[0], B2[1]);
            mma16(acc2[2 * ntp + 1], Aq, B2[2], B2[3]);
        }
    }

    unsigned* C1b = (unsigned*)C1;
    unsigned* C2b = (unsigned*)C2;
#pragma unroll
    for (int nt = 0; nt < 8; nt++) {
        int r = row0 + m0 + g;
        int c = col0 + nt * 8 + 2 * t4;
        size_t i0 = ((size_t)r * ND + c) >> 1;
        size_t i1 = ((size_t)(r + 8) * ND + c) >> 1;
        C1b[i0] = pk(acc1[nt][0], acc1[nt][1]);
        C1b[i1] = pk(acc1[nt][2], acc1[nt][3]);
        C2b[i0] = pk(acc2[nt][0], acc2[nt][1]);
        C2b[i1] = pk(acc2[nt][2], acc2[nt][3]);
    }
}

// ---------------------------------------------------------------------------
// bf16 flash attention -- EXACT R10 configuration (known 119.2 us):
//   hsa = softmax_t(rk.rq^T + sr[t]) @ fr    (no-max ex2 softmax, log2e
//   pre-folded, sl dropped by shift-invariance)
// Block: 128 Q rows, 8 warps x m16, 256 threads, 2 CTAs/SM. 128-key
// double-buffered prefetch tiles (per-buffer byte stride 18432), computed as
// two 64-key halves. P stays in regs: S C-frags re-pack into PV A-frags.
// smem u32: q2[4608] | k2[2x4608] | v2[2x4608] | sr[2x128]
// ---------------------------------------------------------------------------
__global__ __launch_bounds__(256, 2) void attn_bf16(
    const __nv_bfloat16* __restrict__ rk, const __nv_bfloat16* __restrict__ rq,
    const __nv_bfloat16* __restrict__ fr, const float* __restrict__ srb,
    __nv_bfloat16* __restrict__ hsa)
{
    extern __shared__ unsigned smu[];
    unsigned* q2 = smu;                    // [128][36]
    unsigned* k2 = q2 + 4608;              // 2 x [128][36]
    unsigned* v2 = k2 + 2 * 4608;          // 2 x [128][36] natural [t][d]
    float*  sr_s = (float*)(v2 + 2 * 4608);// 2 x [128]

    const int tid = threadIdx.x;
    const int lane = tid & 31, w = tid >> 5;
    const int g = lane >> 2, t4 = lane & 3;
    const int s0 = blockIdx.x * 128;
    const int h = blockIdx.y, b = blockIdx.z;
    const int m0 = w * 16;

    const int rowA = (lane & 7) + ((lane >> 3) & 1) * 8;
    const int prA  = (lane >> 4) * 4;
    const int rowB = (lane & 7) + (lane >> 4) * 8;
    const int prB  = ((lane >> 3) & 1) * 4;
    const uint32_t qS = s2u(q2), kS = s2u(k2), vS = s2u(v2);
    const uint32_t srS = s2u(sr_s);
    const uint32_t qAddr = qS + (((m0 + rowA) * 36 + prA) << 2);
    const uint32_t kAddr = kS + ((rowB * 36 + prB) << 2);
    const uint32_t vAddr = vS + ((rowA * 36 + prA) << 2);   // trans pattern

    const __nv_bfloat16* qg = rk + (size_t)(b * NS + s0) * ND + h * HDIM;
    const __nv_bfloat16* kg = rq + (size_t)b * NS * ND + h * HDIM;
    const __nv_bfloat16* vg = fr + (size_t)b * NS * ND + h * HDIM;
    const float* srr = srb + ((size_t)b * NH + h) * NS;

    auto prefetch = [&](int t0p, int buf) {
#pragma unroll
        for (int p = 0; p < 4; p++) {
            int idx = tid + p * 256;          // 0..1023
            int key = idx >> 3, c = idx & 7;  // key 0..127
            uint32_t off = (uint32_t)((key * 36 + c * 4) << 2);
            size_t goff = (size_t)(t0p + key) * ND + c * 8;
            cpa16(kS + buf * 18432 + off, kg + goff);
            cpa16(vS + buf * 18432 + off, vg + goff);
        }
        if (tid < 32) cpa16(srS + buf * 512 + tid * 16, srr + t0p + tid * 4);
    };

    // Stage Q via cp.async (part of the first wait group)
#pragma unroll
    for (int p = 0; p < 4; p++) {
        int idx = tid + p * 256;
        int r = idx >> 3, c = idx & 7;
        cpa16(qS + ((r * 36 + c * 4) << 2), qg + (size_t)r * ND + c * 8);
    }
    prefetch(0, 0); cpacommit();

    float o[8][4];
    float lsum[2] = {0.f, 0.f};
#pragma unroll
    for (int nt = 0; nt < 8; nt++)
#pragma unroll
        for (int j = 0; j < 4; j++) o[nt][j] = 0.f;

    int pb = 0;
    for (int t0 = 0; t0 < NS; t0 += 128) {
        cpawait(); __syncthreads();
        if (t0 + 128 < NS) { prefetch(t0 + 128, pb ^ 1); cpacommit(); }

#pragma unroll
        for (int half = 0; half < 2; half++) {
            const uint32_t kBase = kAddr + pb * 18432 + half * 9216;
            const uint32_t vBase = vAddr + pb * 18432 + half * 9216;

            // ---- S = Q @ K^T (64 keys) ----
            float s[8][4];
#pragma unroll
            for (int nt = 0; nt < 8; nt++)
#pragma unroll
                for (int j = 0; j < 4; j++) s[nt][j] = 0.f;
#pragma unroll
            for (int ks = 0; ks < 4; ks++) {
                unsigned Aq[4];
                ldm4(Aq, qAddr + ks * 32);
#pragma unroll
                for (int ntp = 0; ntp < 4; ntp++) {
                    unsigned Bk[4];
                    ldm4(Bk, kBase + ntp * (16 * 36 * 4) + ks * 32);
                    mma16(s[2 * ntp],     Aq, Bk[0], Bk[1]);
                    mma16(s[2 * ntp + 1], Aq, Bk[2], Bk[3]);
                }
            }

            // ---- bias + ex2 (no-max softmax; log2e pre-folded) ----
            const float* srt = sr_s + pb * 128 + half * 64;
            unsigned plo[8], phi[8];
#pragma unroll
            for (int nt = 0; nt < 8; nt++) {
                float2 bi = *(const float2*)&srt[nt * 8 + 2 * t4];
                float p0 = ex2(s[nt][0] + bi.x);
                float p1 = ex2(s[nt][1] + bi.y);
                float q0 = ex2(s[nt][2] + bi.x);
                float q1 = ex2(s[nt][3] + bi.y);
                lsum[0] += p0 + p1;
                lsum[1] += q0 + q1;
                plo[nt] = pk(p0, p1);
                phi[nt] = pk(q0, q1);
            }

            // ---- O += P @ V : S C-frags re-pack into PV A-frags ----
#pragma unroll
            for (int ks = 0; ks < 4; ks++) {
                unsigned Ap4[4] = {plo[2 * ks], phi[2 * ks],
                                   plo[2 * ks + 1], phi[2 * ks + 1]};
#pragma unroll
                for (int ntp = 0; ntp < 4; ntp++) {
                    unsigned Bv[4];
                    ldm4t(Bv, vBase + ks * (16 * 36 * 4) + ntp * 32);
                    mma16(o[2 * ntp],     Ap4, Bv[0], Bv[1]);
                    mma16(o[2 * ntp + 1], Ap4, Bv[2], Bv[3]);
                }
            }
        }
        pb ^= 1;
    }

    // Epilogue: deferred row-sum reduce, normalize, store bf16 hsa
#pragma unroll
    for (int i = 0; i < 2; i++) {
        lsum[i] += __shfl_xor_sync(0xffffffffu, lsum[i], 1);
        lsum[i] += __shfl_xor_sync(0xffffffffu, lsum[i], 2);
        lsum[i] = 1.0f / lsum[i];
    }
    unsigned* Hb = (unsigned*)hsa;
#pragma unroll
    for (int nt = 0; nt < 8; nt++) {
        int r = s0 + m0 + g;
        int col = h * HDIM + nt * 8 + 2 * t4;
        Hb[((size_t)(b * NS + r) * ND + col) >> 1] =
            pk(o[nt][0] * lsum[0], o[nt][1] * lsum[0]);
        Hb[((size_t)(b * NS + r + 8) * ND + col) >> 1] =
            pk(o[nt][2] * lsum[1], o[nt][3] * lsum[1]);
    }
}

// ---------------------------------------------------------------------------
// out = LayerNorm(h + fh) * g + b     (one warp per row of 512)
// ---------------------------------------------------------------------------
__global__ void ln_kernel(const float* __restrict__ hin,
                          const float* __restrict__ fh,
                          const float* __restrict__ g,
                          const float* __restrict__ be,
                          float* __restrict__ out)
{
    int warp = threadIdx.x >> 5, lane = threadIdx.x & 31;
    int row = blockIdx.x * 8 + warp;
    const float* hr = hin + (size_t)row * ND;
    const float* fr = fh  + (size_t)row * ND;

    float x[16];
    float sum = 0.f;
#pragma unroll
    for (int i = 0; i < 16; i++) {
        int d = lane + i * 32;
        x[i] = hr[d] + fr[d];
        sum += x[i];
    }
#pragma unroll
    for (int m = 16; m > 0; m >>= 1) sum += __shfl_xor_sync(0xffffffffu, sum, m);
    float mu = sum * (1.0f / ND);
    float vs = 0.f;
#pragma unroll
    for (int i = 0; i < 16; i++) { float d = x[i] - mu; vs += d * d; }
#pragma unroll
    for (int m = 16; m > 0; m >>= 1) vs += __shfl_xor_sync(0xffffffffu, vs, m);
    float rstd = rsqrtf(vs * (1.0f / ND) + LN_EPS);
#pragma unroll
    for (int i = 0; i < 16; i++) {
        int d = lane + i * 32;
        out[(size_t)row * ND + d] = (x[i] - mu) * rstd * g[d] + be[d];
    }
}

// ---------------------------------------------------------------------------
// kernel_launch
// Inputs: 0:h 1:rh 2:Wl(unused) 3:Wr 4:al(unused) 5:ar 6:Wrs 7:Wrt 8:Wf 9:ln_g 10:ln_b
// ---------------------------------------------------------------------------
extern "C" void kernel_launch(void* const* d_in, const int* in_sizes, int n_in,
                              void* d_out, int out_size)
{
    const float* h    = (const float*)d_in[0];
    const float* rh   = (const float*)d_in[1];
    const float* Wr   = (const float*)d_in[3];
    const float* ar   = (const float*)d_in[5];
    const float* Wrs  = (const float*)d_in[6];
    const float* Wrt  = (const float*)d_in[7];
    const float* Wf   = (const float*)d_in[8];
    const float* ln_g = (const float*)d_in[9];
    const float* ln_b = (const float*)d_in[10];
    float* out = (float*)d_out;

    __nv_bfloat16 *hb, *rhb, *wrb, *wrsb, *wrtb, *wfb;
    __nv_bfloat16 *frb, *rkb, *rqb, *hsab;
    float *srb, *fh;
    cudaGetSymbolAddress((void**)&hb,   g_h_bf);
    cudaGetSymbolAddress((void**)&rhb,  g_rh_bf);
    cudaGetSymbolAddress((void**)&wrb,  g_wr);
    cudaGetSymbolAddress((void**)&wrsb, g_wrs);
    cudaGetSymbolAddress((void**)&wrtb, g_wrt);
    cudaGetSymbolAddress((void**)&wfb,  g_wf);
    cudaGetSymbolAddress((void**)&frb,  g_fr_bf);
    cudaGetSymbolAddress((void**)&rkb,  g_rk_bf);
    cudaGetSymbolAddress((void**)&rqb,  g_rq_bf);
    cudaGetSymbolAddress((void**)&hsab, g_hsa_bf);
    cudaGetSymbolAddress((void**)&srb,  g_sr);
    cudaGetSymbolAddress((void**)&fh,   g_fh);

    const int smem_gemm = (2 * 4608 + 2 * 4352) * (int)sizeof(unsigned);     // 71680
    const int smem_attn = (4608 + 2 * 4608 + 2 * 4608 + 256) * 4;            // 93184
    cudaFuncSetAttribute(gemm_bf<true,  true >, cudaFuncAttributeMaxDynamicSharedMemorySize, smem_gemm);
    cudaFuncSetAttribute(gemm_bf<false, false>, cudaFuncAttributeMaxDynamicSharedMemorySize, smem_gemm);
    cudaFuncSetAttribute(attn_bf16, cudaFuncAttributeMaxDynamicSharedMemorySize, smem_attn);

    // Single fused fp32 -> bf16 conversion pass (Wrs pre-scaled by log2e)
    cvt_all<<<N_CVT_TOTAL / 256, 256>>>(h, rh, Wr, Wrs, Wrt, Wf);

    dim3 blk(256);
    dim3 g128(ND / 128, MR / 128);   // 4 x 64 = 256 blocks: one wave at 2/SM
    // fr projection + fused sr epilogue (fl/sl dropped: softmax shift-invariance)
    gemm_bf<true,  true ><<<g128, blk, smem_gemm>>>(hb,  wrb,  frb, ar, srb, MR, ND, ND);
    // rk/rq dual-output projection (shared rh tile)
    gemm_rkq<<<dim3(ND / 64, MR / 128), blk>>>(rhb, wrsb, wrtb, rkb, rqb);
    // bf16 flash attention (exact R10 config)
    attn_bf16<<<dim3(NS / 128, NH, NB), blk, smem_attn>>>(rkb, rqb, frb, srb, hsab);
    // Output projection + residual LayerNorm
    gemm_bf<false, false><<<g128, blk, smem_gemm>>>(hsab, wfb, fh, nullptr, nullptr, MR, ND, ND);
    ln_kernel<<<MR / 8, 256>>>(h, fh, ln_g, ln_b, out);
}

// round 14
// speedup vs baseline: 1.1252x; 1.0060x over previous
#include <cuda_runtime.h>
#include <cuda_bf16.h>
#include <math.h>
#include <stdint.h>

// Problem constants
#define NB 4
#define NS 2048
#define ND 512
#define NH 8
#define HDIM 64
#define RLD 64
#define SLOPE 0.01f
#define LN_EPS 1e-5f
#define MR (NB * NS)   // 8192 rows
#define LOG2E 1.4426950408889634f

// ---------------------------------------------------------------------------
// Scratch (device globals -- no allocation allowed in kernel_launch)
// ---------------------------------------------------------------------------
__device__ __nv_bfloat16 g_h_bf [MR * ND];    // h   -> bf16
__device__ __nv_bfloat16 g_rh_bf[MR * RLD];   // rh  -> bf16
__device__ __nv_bfloat16 g_wr  [ND * ND];     // Wr  -> bf16
__device__ __nv_bfloat16 g_wrs [RLD * ND];    // Wrs*log2e -> bf16
__device__ __nv_bfloat16 g_wrt [RLD * ND];    // Wrt -> bf16
__device__ __nv_bfloat16 g_wf  [ND * ND];     // Wf  -> bf16
__device__ __nv_bfloat16 g_fr_bf [MR * ND];   // h @ Wr   [b,s,h,d]
__device__ __nv_bfloat16 g_rk_bf [MR * ND];   // rh @ (Wrs*log2e)
__device__ __nv_bfloat16 g_rq_bf [MR * ND];   // rh @ Wrt
__device__ __nv_bfloat16 g_hsa_bf[MR * ND];   // attention context
__device__ float g_sr [NB * NH * NS];         // per-key bias * log2e
__device__ float g_fh [MR * ND];              // h_sa @ Wf (fp32 for LN)

// ---------------------------------------------------------------------------
// helpers
// ---------------------------------------------------------------------------
__device__ __forceinline__ unsigned pk(float x, float y) {
    __nv_bfloat162 t = __float22bfloat162_rn(make_float2(x, y));
    return *(unsigned*)&t;
}

__device__ __forceinline__ float ex2(float x) {
    float y;
    asm("ex2.approx.f32 %0, %1;" : "=f"(y) : "f"(x));
    return y;
}

__device__ __forceinline__ void mma16(float* c, const unsigned* a,
                                      unsigned b0, unsigned b1) {
    asm volatile(
        "mma.sync.aligned.m16n8k16.row.col.f32.bf16.bf16.f32 "
        "{%0,%1,%2,%3}, {%4,%5,%6,%7}, {%8,%9}, {%0,%1,%2,%3};"
        : "+f"(c[0]), "+f"(c[1]), "+f"(c[2]), "+f"(c[3])
        : "r"(a[0]), "r"(a[1]), "r"(a[2]), "r"(a[3]), "r"(b0), "r"(b1));
}

__device__ __forceinline__ void ldm4(unsigned* r, uint32_t addr) {
    asm volatile(
        "ldmatrix.sync.aligned.m8n8.x4.shared.b16 {%0,%1,%2,%3}, [%4];"
        : "=r"(r[0]), "=r"(r[1]), "=r"(r[2]), "=r"(r[3]) : "r"(addr));
}

__device__ __forceinline__ void ldm4t(unsigned* r, uint32_t addr) {
    asm volatile(
        "ldmatrix.sync.aligned.m8n8.x4.trans.shared.b16 {%0,%1,%2,%3}, [%4];"
        : "=r"(r[0]), "=r"(r[1]), "=r"(r[2]), "=r"(r[3]) : "r"(addr));
}

__device__ __forceinline__ uint32_t s2u(const void* p) {
    return (uint32_t)__cvta_generic_to_shared(p);
}

__device__ __forceinline__ void cpa16(uint32_t smem, const void* g) {
    asm volatile("cp.async.cg.shared.global [%0], [%1], 16;" :: "r"(smem), "l"(g));
}
__device__ __forceinline__ void cpacommit() {
    asm volatile("cp.async.commit_group;");
}
__device__ __forceinline__ void cpawait() {
    asm volatile("cp.async.wait_group 0;" ::: "memory");
}

__device__ __forceinline__ float leaky(float x) {
    return x >= 0.f ? x : SLOPE * x;
}

// ---------------------------------------------------------------------------
// Fused fp32 -> bf16 conversion for all six operands (one launch).
// Segment sizes in float4 units; Wrs is pre-scaled by log2(e).
// ---------------------------------------------------------------------------
#define N_H4   1048576   // MR*ND/4
#define N_RH4  131072    // MR*RLD/4
#define N_WR4  65536     // ND*ND/4
#define N_WS4  8192      // RLD*ND/4
#define N_WT4  8192
#define N_WF4  65536
#define N_CVT_TOTAL (N_H4 + N_RH4 + N_WR4 + N_WS4 + N_WT4 + N_WF4)  // 1327104

__global__ void cvt_all(const float* __restrict__ h, const float* __restrict__ rh,
                        const float* __restrict__ Wr, const float* __restrict__ Wrs,
                        const float* __restrict__ Wrt, const float* __restrict__ Wf)
{
    int j = blockIdx.x * 256 + threadIdx.x;
    const float* src;
    __nv_bfloat16* dst;
    float scale = 1.f;
    if (j < N_H4)                 { src = h;   dst = g_h_bf; }
    else if ((j -= N_H4) < N_RH4) { src = rh;  dst = g_rh_bf; }
    else if ((j -= N_RH4) < N_WR4){ src = Wr;  dst = g_wr; }
    else if ((j -= N_WR4) < N_WS4){ src = Wrs; dst = g_wrs; scale = LOG2E; }
    else if ((j -= N_WS4) < N_WT4){ src = Wrt; dst = g_wrt; }
    else                          { j -= N_WT4; src = Wf; dst = g_wf; }
    float4 v = *(const float4*)(src + (size_t)j * 4);
    uint2 u; u.x = pk(v.x * scale, v.y * scale); u.y = pk(v.z * scale, v.w * scale);
    *(uint2*)(dst + (size_t)j * 4) = u;
}

// ---------------------------------------------------------------------------
// bf16 tensor-core GEMM: C[M,N] = A[M,K] @ W[K,N], all-bf16 operands.
// Block 128x128 (one wave for M=8192,N=512), BK=64, 256 threads = 8 warps
// (warp = m16 x n128, acc 64 regs). cp.async double-buffered.
// A [row][k-pair] pitch 36 wds; W natural [k][n] pitch 68 wds via
// ldmatrix.x4.trans (pitch = 4 mod 32 words -> conflict-free).
// DO_SR: N-tile spans TWO heads (2 x HDIM); epilogue splits at nt=8.
// ---------------------------------------------------------------------------
template<bool OUT_BF, bool DO_SR>
__global__ __launch_bounds__(256) void gemm_bf(
    const __nv_bfloat16* __restrict__ A, const __nv_bfloat16* __restrict__ Wb,
    void* __restrict__ Cp, const float* __restrict__ ar,
    float* __restrict__ srb, int M, int N, int K)
{
    extern __shared__ unsigned smu[];
    unsigned* a2 = smu;              // 2 x 4608  (buffer stride 18432 B)
    unsigned* w2 = smu + 2 * 4608;   // 2 x 4352  (buffer stride 17408 B)
    const int tid = threadIdx.x;
    const int lane = tid & 31, w = tid >> 5;
    const int g = lane >> 2, t4 = lane & 3;
    const int row0 = blockIdx.y * 128, col0 = blockIdx.x * 128;
    const int m0 = w * 16;

    const int rowA = (lane & 7) + ((lane >> 3) & 1) * 8;
    const int prA  = (lane >> 4) * 4;
    const uint32_t aS = s2u(a2), wS = s2u(w2);
    const uint32_t aAddr = aS + (((m0 + rowA) * 36 + prA) << 2);
    const uint32_t wAddr = wS + ((rowA * 68 + prA) << 2);   // trans pattern

    auto prefetch = [&](int k0, int buf) {
#pragma unroll
        for (int p = 0; p < 4; p++) {          // A: 128 rows x 64 k
            int idx = tid + p * 256;
            int r = idx >> 3, c = idx & 7;
            cpa16(aS + buf * 18432 + ((r * 36 + c * 4) << 2),
                  A + (size_t)(row0 + r) * K + k0 + c * 8);
        }
#pragma unroll
        for (int p = 0; p < 4; p++) {          // W: 64 k x 128 n
            int idx = tid + p * 256;
            int r = idx >> 4, c = idx & 15;
            cpa16(wS + buf * 17408 + ((r * 68 + c * 4) << 2),
                  Wb + (size_t)(k0 + r) * N + col0 + c * 8);
        }
    };

    float acc[16][4];
#pragma unroll
    for (int nt = 0; nt < 16; nt++)
#pragma unroll
        for (int j = 0; j < 4; j++) acc[nt][j] = 0.f;

    prefetch(0, 0); cpacommit();
    int pb = 0;
    const int KT = K >> 6;
    for (int kt = 0; kt < KT; kt++) {
        cpawait(); __syncthreads();
        if (kt + 1 < KT) { prefetch((kt + 1) * 64, pb ^ 1); cpacommit(); }
#pragma unroll
        for (int ks = 0; ks < 4; ks++) {
            unsigned Aq[4];
            ldm4(Aq, aAddr + pb * 18432 + ks * 32);
#pragma unroll
            for (int ntp = 0; ntp < 8; ntp++) {
                unsigned Bw[4];
                ldm4t(Bw, wAddr + pb * 17408 + ks * 4352 + ntp * 32);
                mma16(acc[2 * ntp],     Aq, Bw[0], Bw[1]);
                mma16(acc[2 * ntp + 1], Aq, Bw[2], Bw[3]);
            }
        }
        pb ^= 1;
    }

    if (OUT_BF) {
        unsigned* Cb = (unsigned*)Cp;
#pragma unroll
        for (int nt = 0; nt < 16; nt++) {
            int r = row0 + m0 + g;
            int c = col0 + nt * 8 + 2 * t4;
            Cb[((size_t)r * N + c) >> 1] = pk(acc[nt][0], acc[nt][1]);
            Cb[((size_t)(r + 8) * N + c) >> 1] = pk(acc[nt][2], acc[nt][3]);
        }
    } else {
        float* Cf = (float*)Cp;
#pragma unroll
        for (int nt = 0; nt < 16; nt++) {
            int r = row0 + m0 + g;
            int c = col0 + nt * 8 + 2 * t4;
            float2 lo; lo.x = acc[nt][0]; lo.y = acc[nt][1];
            float2 hi; hi.x = acc[nt][2]; hi.y = acc[nt][3];
            *(float2*)(Cf + (size_t)r * N + c) = lo;
            *(float2*)(Cf + (size_t)(r + 8) * N + c) = hi;
        }
    }

    if (DO_SR) {
        // N-tile = 2 heads: head hh = col0/64 + (nt>=8); d = (nt&7)*8 + 2*t4
        float sm[2][2] = {{0.f, 0.f}, {0.f, 0.f}};
#pragma unroll
        for (int nt = 0; nt < 16; nt++) {
            int hh = nt >> 3;
            float2 av = *(const float2*)&ar[(nt & 7) * 8 + 2 * t4];
            sm[hh][0] += leaky(acc[nt][0]) * av.x + leaky(acc[nt][1]) * av.y;
            sm[hh][1] += leaky(acc[nt][2]) * av.x + leaky(acc[nt][3]) * av.y;
        }
#pragma unroll
        for (int hh = 0; hh < 2; hh++)
#pragma unroll
            for (int i = 0; i < 2; i++) {
                sm[hh][i] += __shfl_xor_sync(0xffffffffu, sm[hh][i], 1);
                sm[hh][i] += __shfl_xor_sync(0xffffffffu, sm[hh][i], 2);
            }
        if (t4 == 0) {
            int hbase = col0 / HDIM;
#pragma unroll
            for (int hh = 0; hh < 2; hh++)
#pragma unroll
                for (int i = 0; i < 2; i++) {
                    int r = row0 + m0 + i * 8 + g;
                    int bb = r >> 11, t = r & (NS - 1);
                    srb[((size_t)bb * NH + hbase + hh) * NS + t] = sm[hh][i] * LOG2E;
                }
        }
    }
}

// ---------------------------------------------------------------------------
// Dual-output K=64 GEMM: rk = rh @ Wrs', rq = rh @ Wrt  (shared A tile).
// Block 128 rows x 64 cols, 256 threads = 8 warps (warp = m16 x n64).
// ---------------------------------------------------------------------------
__global__ __launch_bounds__(256) void gemm_rkq(
    const __nv_bfloat16* __restrict__ A,
    const __nv_bfloat16* __restrict__ W1, const __nv_bfloat16* __restrict__ W2,
    __nv_bfloat16* __restrict__ C1, __nv_bfloat16* __restrict__ C2)
{
    __shared__ unsigned a2[4608];
    __shared__ unsigned w1[2304];
    __shared__ unsigned w2[2304];
    const int tid = threadIdx.x;
    const int lane = tid & 31, w = tid >> 5;
    const int g = lane >> 2, t4 = lane & 3;
    const int row0 = blockIdx.y * 128, col0 = blockIdx.x * 64;
    const int m0 = w * 16;

    const int rowA = (lane & 7) + ((lane >> 3) & 1) * 8;
    const int prA  = (lane >> 4) * 4;
    const uint32_t aS = s2u(a2), w1S = s2u(w1), w2S = s2u(w2);
    const uint32_t aAddr  = aS  + (((m0 + rowA) * 36 + prA) << 2);
    const uint32_t w1Addr = w1S + ((rowA * 36 + prA) << 2);
    const uint32_t w2Addr = w2S + ((rowA * 36 + prA) << 2);

#pragma unroll
    for (int p = 0; p < 4; p++) {
        int idx = tid + p * 256;
        int r = idx >> 3, c = idx & 7;
        cpa16(aS + ((r * 36 + c * 4) << 2), A + (size_t)(row0 + r) * RLD + c * 8);
    }
#pragma unroll
    for (int p = 0; p < 2; p++) {
        int idx = tid + p * 256;
        int r = idx >> 3, c = idx & 7;
        uint32_t off = (uint32_t)((r * 36 + c * 4) << 2);
        size_t goff = (size_t)r * ND + col0 + c * 8;
        cpa16(w1S + off, W1 + goff);
        cpa16(w2S + off, W2 + goff);
    }
    cpacommit(); cpawait(); __syncthreads();

    float acc1[8][4], acc2[8][4];
#pragma unroll
    for (int nt = 0; nt < 8; nt++)
#pragma unroll
        for (int j = 0; j < 4; j++) { acc1[nt][j] = 0.f; acc2[nt][j] = 0.f; }

#pragma unroll
    for (int ks = 0; ks < 4; ks++) {
        unsigned Aq[4];
        ldm4(Aq, aAddr + ks * 32);
#pragma unroll
        for (int ntp = 0; ntp < 4; ntp++) {
            unsigned B1[4], B2[4];
            ldm4t(B1, w1Addr + ks * 2304 + ntp * 32);
            ldm4t(B2, w2Addr + ks * 2304 + ntp * 32);
            mma16(acc1[2 * ntp],     Aq, B1[0], B1[1]);
            mma16(acc1[2 * ntp + 1], Aq, B1[2], B1[3]);
            mma16(acc2[2 * ntp],     Aq, B2[0], B2[1]);
            mma16(acc2[2 * ntp + 1], Aq, B2[2], B2[3]);
        }
    }

    unsigned* C1b = (unsigned*)C1;
    unsigned* C2b = (unsigned*)C2;
#pragma unroll
    for (int nt = 0; nt < 8; nt++) {
        int r = row0 + m0 + g;
        int c = col0 + nt * 8 + 2 * t4;
        size_t i0 = ((size_t)r * ND + c) >> 1;
        size_t i1 = ((size_t)(r + 8) * ND + c) >> 1;
        C1b[i0] = pk(acc1[nt][0], acc1[nt][1]);
        C1b[i1] = pk(acc1[nt][2], acc1[nt][3]);
        C2b[i0] = pk(acc2[nt][0], acc2[nt][1]);
        C2b[i1] = pk(acc2[nt][2], acc2[nt][3]);
    }
}

// ---------------------------------------------------------------------------
// bf16 flash attention (no-max ex2 softmax, log2e pre-folded, sl dropped):
//   hsa = softmax_t(rk.rq^T + sr[t]) @ fr
// R14: Q fragments hoisted to registers (loaded ONCE -- Q is tile-invariant,
// deletes 128 LDSM/warp), and exp->PV streamed per ks-chunk (live packed-P
// drops 16->4 regs, MUFU overlaps tensor). Otherwise exact R10/R13 config:
// 128 Q rows, 8 warps x m16, 256 threads, 2 CTAs/SM, 128-key double-buffered
// tiles (byte stride 18432) computed as two 64-key halves.
// smem u32: q2[4608] | k2[2x4608] | v2[2x4608] | sr[2x128]
// ---------------------------------------------------------------------------
__global__ __launch_bounds__(256, 2) void attn_bf16(
    const __nv_bfloat16* __restrict__ rk, const __nv_bfloat16* __restrict__ rq,
    const __nv_bfloat16* __restrict__ fr, const float* __restrict__ srb,
    __nv_bfloat16* __restrict__ hsa)
{
    extern __shared__ unsigned smu[];
    unsigned* q2 = smu;                    // [128][36]
    unsigned* k2 = q2 + 4608;              // 2 x [128][36]
    unsigned* v2 = k2 + 2 * 4608;          // 2 x [128][36] natural [t][d]
    float*  sr_s = (float*)(v2 + 2 * 4608);// 2 x [128]

    const int tid = threadIdx.x;
    const int lane = tid & 31, w = tid >> 5;
    const int g = lane >> 2, t4 = lane & 3;
    const int s0 = blockIdx.x * 128;
    const int h = blockIdx.y, b = blockIdx.z;
    const int m0 = w * 16;

    const int rowA = (lane & 7) + ((lane >> 3) & 1) * 8;
    const int prA  = (lane >> 4) * 4;
    const int rowB = (lane & 7) + (lane >> 4) * 8;
    const int prB  = ((lane >> 3) & 1) * 4;
    const uint32_t qS = s2u(q2), kS = s2u(k2), vS = s2u(v2);
    const uint32_t srS = s2u(sr_s);
    const uint32_t qAddr = qS + (((m0 + rowA) * 36 + prA) << 2);
    const uint32_t kAddr = kS + ((rowB * 36 + prB) << 2);
    const uint32_t vAddr = vS + ((rowA * 36 + prA) << 2);   // trans pattern

    const __nv_bfloat16* qg = rk + (size_t)(b * NS + s0) * ND + h * HDIM;
    const __nv_bfloat16* kg = rq + (size_t)b * NS * ND + h * HDIM;
    const __nv_bfloat16* vg = fr + (size_t)b * NS * ND + h * HDIM;
    const float* srr = srb + ((size_t)b * NH + h) * NS;

    auto prefetch = [&](int t0p, int buf) {
#pragma unroll
        for (int p = 0; p < 4; p++) {
            int idx = tid + p * 256;          // 0..1023
            int key = idx >> 3, c = idx & 7;  // key 0..127
            uint32_t off = (uint32_t)((key * 36 + c * 4) << 2);
            size_t goff = (size_t)(t0p + key) * ND + c * 8;
            cpa16(kS + buf * 18432 + off, kg + goff);
            cpa16(vS + buf * 18432 + off, vg + goff);
        }
        if (tid < 32) cpa16(srS + buf * 512 + tid * 16, srr + t0p + tid * 4);
    };

    // Stage Q via cp.async (part of the first wait group)
#pragma unroll
    for (int p = 0; p < 4; p++) {
        int idx = tid + p * 256;
        int r = idx >> 3, c = idx & 7;
        cpa16(qS + ((r * 36 + c * 4) << 2), qg + (size_t)r * ND + c * 8);
    }
    prefetch(0, 0); cpacommit();
    cpawait(); __syncthreads();

    // Hoist Q fragments: tile-invariant, loaded exactly once.
    unsigned qf[4][4];
#pragma unroll
    for (int ks = 0; ks < 4; ks++) ldm4(qf[ks], qAddr + ks * 32);

    float o[8][4];
    float lsum[2] = {0.f, 0.f};
#pragma unroll
    for (int nt = 0; nt < 8; nt++)
#pragma unroll
        for (int j = 0; j < 4; j++) o[nt][j] = 0.f;

    int pb = 0;
    for (int t0 = 0; t0 < NS; t0 += 128) {
        if (t0 > 0) { cpawait(); __syncthreads(); }
        if (t0 + 128 < NS) { prefetch(t0 + 128, pb ^ 1); cpacommit(); }

#pragma unroll
        for (int half = 0; half < 2; half++) {
            const uint32_t kBase = kAddr + pb * 18432 + half * 9216;
            const uint32_t vBase = vAddr + pb * 18432 + half * 9216;

            // ---- S = Q @ K^T (64 keys), Q-frags from registers ----
            float s[8][4];
#pragma unroll
            for (int nt = 0; nt < 8; nt++)
#pragma unroll
                for (int j = 0; j < 4; j++) s[nt][j] = 0.f;
#pragma unroll
            for (int ks = 0; ks < 4; ks++) {
#pragma unroll
                for (int ntp = 0; ntp < 4; ntp++) {
                    unsigned Bk[4];
                    ldm4(Bk, kBase + ntp * (16 * 36 * 4) + ks * 32);
                    mma16(s[2 * ntp],     qf[ks], Bk[0], Bk[1]);
                    mma16(s[2 * ntp + 1], qf[ks], Bk[2], Bk[3]);
                }
            }

            // ---- streamed bias + ex2 -> PV per ks-chunk of 16 keys ----
            const float* srt = sr_s + pb * 128 + half * 64;
#pragma unroll
            for (int ks = 0; ks < 4; ks++) {
                float2 bi0 = *(const float2*)&srt[(2 * ks) * 8 + 2 * t4];
                float2 bi1 = *(const float2*)&srt[(2 * ks + 1) * 8 + 2 * t4];
                float p0 = ex2(s[2 * ks][0] + bi0.x);
                float p1 = ex2(s[2 * ks][1] + bi0.y);
                float p2 = ex2(s[2 * ks][2] + bi0.x);
                float p3 = ex2(s[2 * ks][3] + bi0.y);
                float q0 = ex2(s[2 * ks + 1][0] + bi1.x);
                float q1 = ex2(s[2 * ks + 1][1] + bi1.y);
                float q2 = ex2(s[2 * ks + 1][2] + bi1.x);
                float q3 = ex2(s[2 * ks + 1][3] + bi1.y);
                lsum[0] += p0 + p1 + q0 + q1;
                lsum[1] += p2 + p3 + q2 + q3;
                unsigned Ap4[4] = {pk(p0, p1), pk(p2, p3), pk(q0, q1), pk(q2, q3)};
#pragma unroll
                for (int ntp = 0; ntp < 4; ntp++) {
                    unsigned Bv[4];
                    ldm4t(Bv, vBase + ks * (16 * 36 * 4) + ntp * 32);
                    mma16(o[2 * ntp],     Ap4, Bv[0], Bv[1]);
                    mma16(o[2 * ntp + 1], Ap4, Bv[2], Bv[3]);
                }
            }
        }
        pb ^= 1;
    }

    // Epilogue: deferred row-sum reduce, normalize, store bf16 hsa
#pragma unroll
    for (int i = 0; i < 2; i++) {
        lsum[i] += __shfl_xor_sync(0xffffffffu, lsum[i], 1);
        lsum[i] += __shfl_xor_sync(0xffffffffu, lsum[i], 2);
        lsum[i] = 1.0f / lsum[i];
    }
    unsigned* Hb = (unsigned*)hsa;
#pragma unroll
    for (int nt = 0; nt < 8; nt++) {
        int r = s0 + m0 + g;
        int col = h * HDIM + nt * 8 + 2 * t4;
        Hb[((size_t)(b * NS + r) * ND + col) >> 1] =
            pk(o[nt][0] * lsum[0], o[nt][1] * lsum[0]);
        Hb[((size_t)(b * NS + r + 8) * ND + col) >> 1] =
            pk(o[nt][2] * lsum[1], o[nt][3] * lsum[1]);
    }
}

// ---------------------------------------------------------------------------
// out = LayerNorm(h + fh) * g + b     (one warp per row of 512)
// ---------------------------------------------------------------------------
__global__ void ln_kernel(const float* __restrict__ hin,
                          const float* __restrict__ fh,
                          const float* __restrict__ g,
                          const float* __restrict__ be,
                          float* __restrict__ out)
{
    int warp = threadIdx.x >> 5, lane = threadIdx.x & 31;
    int row = blockIdx.x * 8 + warp;
    const float* hr = hin + (size_t)row * ND;
    const float* fr = fh  + (size_t)row * ND;

    float x[16];
    float sum = 0.f;
#pragma unroll
    for (int i = 0; i < 16; i++) {
        int d = lane + i * 32;
        x[i] = hr[d] + fr[d];
        sum += x[i];
    }
#pragma unroll
    for (int m = 16; m > 0; m >>= 1) sum += __shfl_xor_sync(0xffffffffu, sum, m);
    float mu = sum * (1.0f / ND);
    float vs = 0.f;
#pragma unroll
    for (int i = 0; i < 16; i++) { float d = x[i] - mu; vs += d * d; }
#pragma unroll
    for (int m = 16; m > 0; m >>= 1) vs += __shfl_xor_sync(0xffffffffu, vs, m);
    float rstd = rsqrtf(vs * (1.0f / ND) + LN_EPS);
#pragma unroll
    for (int i = 0; i < 16; i++) {
        int d = lane + i * 32;
        out[(size_t)row * ND + d] = (x[i] - mu) * rstd * g[d] + be[d];
    }
}

// ---------------------------------------------------------------------------
// kernel_launch
// Inputs: 0:h 1:rh 2:Wl(unused) 3:Wr 4:al(unused) 5:ar 6:Wrs 7:Wrt 8:Wf 9:ln_g 10:ln_b
// ---------------------------------------------------------------------------
extern "C" void kernel_launch(void* const* d_in, const int* in_sizes, int n_in,
                              void* d_out, int out_size)
{
    const float* h    = (const float*)d_in[0];
    const float* rh   = (const float*)d_in[1];
    const float* Wr   = (const float*)d_in[3];
    const float* ar   = (const float*)d_in[5];
    const float* Wrs  = (const float*)d_in[6];
    const float* Wrt  = (const float*)d_in[7];
    const float* Wf   = (const float*)d_in[8];
    const float* ln_g = (const float*)d_in[9];
    const float* ln_b = (const float*)d_in[10];
    float* out = (float*)d_out;

    __nv_bfloat16 *hb, *rhb, *wrb, *wrsb, *wrtb, *wfb;
    __nv_bfloat16 *frb, *rkb, *rqb, *hsab;
    float *srb, *fh;
    cudaGetSymbolAddress((void**)&hb,   g_h_bf);
    cudaGetSymbolAddress((void**)&rhb,  g_rh_bf);
    cudaGetSymbolAddress((void**)&wrb,  g_wr);
    cudaGetSymbolAddress((void**)&wrsb, g_wrs);
    cudaGetSymbolAddress((void**)&wrtb, g_wrt);
    cudaGetSymbolAddress((void**)&wfb,  g_wf);
    cudaGetSymbolAddress((void**)&frb,  g_fr_bf);
    cudaGetSymbolAddress((void**)&rkb,  g_rk_bf);
    cudaGetSymbolAddress((void**)&rqb,  g_rq_bf);
    cudaGetSymbolAddress((void**)&hsab, g_hsa_bf);
    cudaGetSymbolAddress((void**)&srb,  g_sr);
    cudaGetSymbolAddress((void**)&fh,   g_fh);

    const int smem_gemm = (2 * 4608 + 2 * 4352) * (int)sizeof(unsigned);     // 71680
    const int smem_attn = (4608 + 2 * 4608 + 2 * 4608 + 256) * 4;            // 93184
    cudaFuncSetAttribute(gemm_bf<true,  true >, cudaFuncAttributeMaxDynamicSharedMemorySize, smem_gemm);
    cudaFuncSetAttribute(gemm_bf<false, false>, cudaFuncAttributeMaxDynamicSharedMemorySize, smem_gemm);
    cudaFuncSetAttribute(attn_bf16, cudaFuncAttributeMaxDynamicSharedMemorySize, smem_attn);

    // Single fused fp32 -> bf16 conversion pass (Wrs pre-scaled by log2e)
    cvt_all<<<N_CVT_TOTAL / 256, 256>>>(h, rh, Wr, Wrs, Wrt, Wf);

    dim3 blk(256);
    dim3 g128(ND / 128, MR / 128);   // 4 x 64 = 256 blocks: one wave at 2/SM
    // fr projection + fused sr epilogue (fl/sl dropped: softmax shift-invariance)
    gemm_bf<true,  true ><<<g128, blk, smem_gemm>>>(hb,  wrb,  frb, ar, srb, MR, ND, ND);
    // rk/rq dual-output projection (shared rh tile)
    gemm_rkq<<<dim3(ND / 64, MR / 128), blk>>>(rhb, wrsb, wrtb, rkb, rqb);
    // bf16 flash attention (Q-frags in regs + streamed exp->PV)
    attn_bf16<<<dim3(NS / 128, NH, NB), blk, smem_attn>>>(rkb, rqb, frb, srb, hsab);
    // Output projection + residual LayerNorm
    gemm_bf<false, false><<<g128, blk, smem_gemm>>>(hsab, wfb, fh, nullptr, nullptr, MR, ND, ND);
    ln_kernel<<<MR / 8, 256>>>(h, fh, ln_g, ln_b, out);
}